// round 14
// baseline (speedup 1.0000x reference)
#include <cuda_runtime.h>
#include <cuda_fp16.h>
#include <cstdint>

#define N_NODES 100000
#define KNBR    16
#define D       128
#define GM      782
#define LBLK    1563             // ceil(N/64)

__device__ unsigned g_xproj [(size_t)N_NODES * 256];   // fp16x2 pairs
__device__ float    g_hneigh[(size_t)N_NODES * D];
__device__ float    g_tmp   [(size_t)N_NODES * D];
__device__ float    g_tmp2  [(size_t)N_NODES * D];
__device__ float    g_psum  [GM * D];
__device__ float    g_psq   [GM * D];
__device__ float    g_stats [2 * D];

__device__ __forceinline__ float tanha(float x) {
    float r; asm("tanh.approx.f32 %0, %1;" : "=f"(r) : "f"(x)); return r;
}
__device__ __forceinline__ float sig_t(float x) {
    return fmaf(tanha(0.5f * x), 0.5f, 0.5f);
}
__device__ __forceinline__ unsigned pk_f16(float lo, float hi) {
    unsigned r; asm("cvt.rn.f16x2.f32 %0, %1, %2;" : "=r"(r) : "f"(hi), "f"(lo));
    return r;
}
__device__ __forceinline__ float2 hf2f(unsigned u) {
    __half2 h = *reinterpret_cast<__half2*>(&u);
    return __half22float2(h);
}
// f32-accumulate mma
__device__ __forceinline__ void mma_f16(float* d, const unsigned* a,
                                        unsigned b0, unsigned b1) {
    asm volatile(
        "mma.sync.aligned.m16n8k16.row.col.f32.f16.f16.f32 "
        "{%0,%1,%2,%3}, {%4,%5,%6,%7}, {%8,%9}, {%0,%1,%2,%3};"
        : "+f"(d[0]), "+f"(d[1]), "+f"(d[2]), "+f"(d[3])
        : "r"(a[0]), "r"(a[1]), "r"(a[2]), "r"(a[3]), "r"(b0), "r"(b1));
}
// f16-accumulate mma (D/C are 2x b32 = f16x2 pairs)
__device__ __forceinline__ void mma_f16a(unsigned* d, const unsigned* a,
                                         unsigned b0, unsigned b1) {
    asm volatile(
        "mma.sync.aligned.m16n8k16.row.col.f16.f16.f16.f16 "
        "{%0,%1}, {%2,%3,%4,%5}, {%6,%7}, {%0,%1};"
        : "+r"(d[0]), "+r"(d[1])
        : "r"(a[0]), "r"(a[1]), "r"(a[2]), "r"(a[3]), "r"(b0), "r"(b1));
}
__device__ __forceinline__ float4 bn4(float4 v, int c0,
                                      const float* st, const float* gm,
                                      const float* bt) {
    float* p = (float*)&v;
#pragma unroll
    for (int e = 0; e < 4; e++) {
        float y = (p[e] - st[c0 + e]) * st[128 + c0 + e] * gm[c0 + e] + bt[c0 + e];
        p[e] = fmaxf(y, 0.f);
    }
    return v;
}

__global__ void noop_kernel() {}

// ---------------- proj: fp16 SIMT mma (optional fused BN+ReLU on A) --------
__global__ __launch_bounds__(256) void proj_f16_kernel(
    const float* __restrict__ A, const float* __restrict__ W,
    const float* __restrict__ b1, const float* __restrict__ b2,
    unsigned* __restrict__ C,
    const float* __restrict__ bst, const float* __restrict__ bgm,
    const float* __restrict__ bbt)
{
    __shared__ unsigned xa[128 * 68];
    __shared__ unsigned Wb[64 * 132];
    __shared__ float    bsm[128];
    const int tid = threadIdx.x, w = tid >> 5, lane = tid & 31;
    const int g4 = lane >> 2, t4 = lane & 3;
    const int m0 = blockIdx.x * 128, n0 = blockIdx.y * 128;

    for (int i = tid; i < 128 * 32; i += 256) {
        int row = i >> 5, q = i & 31, gm = m0 + row;
        float4 v = make_float4(0.f, 0.f, 0.f, 0.f);
        if (gm < N_NODES) {
            v = *(const float4*)(A + (size_t)gm * 128 + q * 4);
            if (bst) v = bn4(v, q * 4, bst, bgm, bbt);
        }
        xa[row * 68 + q * 2]     = pk_f16(v.x, v.y);
        xa[row * 68 + q * 2 + 1] = pk_f16(v.z, v.w);
    }
    for (int i = tid; i < 128 * 32; i += 256) {
        int n = i >> 5, q = i & 31;
        float4 v = *(const float4*)(W + (size_t)(n0 + n) * 128 + q * 4);
        Wb[(q * 2)     * 132 + n] = pk_f16(v.x, v.y);
        Wb[(q * 2 + 1) * 132 + n] = pk_f16(v.z, v.w);
    }
    if (tid < 128) bsm[tid] = b1[n0 + tid] + b2[n0 + tid];
    __syncthreads();

    float d[8][2][4];
#pragma unroll
    for (int mt = 0; mt < 8; mt++)
#pragma unroll
        for (int nt = 0; nt < 2; nt++)
#pragma unroll
            for (int e = 0; e < 4; e++) d[mt][nt][e] = 0.f;

#pragma unroll
    for (int c = 0; c < 8; c++) {
        const int k0 = c * 8 + t4;
        unsigned a[8][4];
#pragma unroll
        for (int mt = 0; mt < 8; mt++) {
            int rb = (mt * 16 + g4) * 68;
            a[mt][0] = xa[rb + k0];
            a[mt][1] = xa[rb + 8 * 68 + k0];
            a[mt][2] = xa[rb + k0 + 4];
            a[mt][3] = xa[rb + 8 * 68 + k0 + 4];
        }
#pragma unroll
        for (int nt = 0; nt < 2; nt++) {
            int n = w * 16 + nt * 8 + g4;
            unsigned bb0 = Wb[k0 * 132 + n];
            unsigned bb1 = Wb[(k0 + 4) * 132 + n];
#pragma unroll
            for (int mt = 0; mt < 8; mt++) mma_f16(d[mt][nt], a[mt], bb0, bb1);
        }
    }
#pragma unroll
    for (int mt = 0; mt < 8; mt++)
#pragma unroll
        for (int nt = 0; nt < 2; nt++) {
            int col = w * 16 + nt * 8 + t4 * 2;
            float bx = bsm[col], by = bsm[col + 1];
            int cp = (n0 + col) >> 1;
            int gm0 = m0 + mt * 16 + g4, gm1 = gm0 + 8;
            if (gm0 < N_NODES)
                C[(size_t)gm0 * 256 + cp] = pk_f16(d[mt][nt][0] + bx, d[mt][nt][1] + by);
            if (gm1 < N_NODES)
                C[(size_t)gm1 * 256 + cp] = pk_f16(d[mt][nt][2] + bx, d[mt][nt][3] + by);
        }
}

// ---------------- lstm: R11 structure; f16-acc mma t<15, f32-acc final ----
#define WFS 516
#define AFS 34
#define WF_U32 (32 * WFS * 2)
#define AF_OFF WF_U32
#define AF_U32 (2 * 32 * AFS * 4)
#define NB_OFF (WF_U32 + AF_U32)
#define LSTM_SMEM_BYTES ((NB_OFF + 64 * KNBR) * 4)

__global__ __launch_bounds__(512, 1) void lstm_f16_kernel(
    const unsigned* __restrict__ xproj,  // [N,256] fp16x2, biases folded in
    const int*      __restrict__ nbr,
    const float*    __restrict__ Whh,    // [512,128]
    float*          __restrict__ hout)
{
    extern __shared__ unsigned smu[];
    unsigned* Wf  = smu;
    uint4*    Af  = (uint4*)(smu + AF_OFF);
    int*      nbs = (int*)(smu + NB_OFF);

    const int tid  = threadIdx.x;
    const int w    = tid >> 5;
    const int lane = tid & 31;
    const int g4   = lane >> 2;
    const int t4   = lane & 3;
    const int g    = w & 1;
    const int wc   = w >> 1;
    const int base = blockIdx.x * 64;

    for (int i = tid; i < 64 * KNBR; i += 512) {
        int nid = base + (i >> 4);
        if (nid >= N_NODES) nid = N_NODES - 1;
        nbs[i] = nbr[(size_t)nid * KNBR + (i & 15)];
    }
    {
        const float4* wp = (const float4*)(Whh + (size_t)tid * 128);
#pragma unroll 8
        for (int q = 0; q < 32; q++) {
            float4 v = wp[q];
            int kp0 = 2 * q, kp1 = 2 * q + 1;
            Wf[(((kp0 >> 3) * 4 + (kp0 & 3)) * WFS + tid) * 2 + ((kp0 >> 2) & 1)]
                = pk_f16(v.x, v.y);
            Wf[(((kp1 >> 3) * 4 + (kp1 & 3)) * WFS + tid) * 2 + ((kp1 >> 2) & 1)]
                = pk_f16(v.z, v.w);
        }
    }
    __syncthreads();

    float cst[2][2][4];
#pragma unroll
    for (int mt = 0; mt < 2; mt++)
#pragma unroll
        for (int j = 0; j < 2; j++)
#pragma unroll
            for (int e = 0; e < 4; e++) cst[mt][j][e] = 0.f;

    const int r0b = g * 32 + g4;

    // ---- steps 0..14: f16-accumulate mma ----
#pragma unroll 1
    for (int t = 0; t < KNBR - 1; t++) {
        unsigned d16[2][8][2];
        // z init: raw copy — gathered f16x2 pair IS the D-fragment word
#pragma unroll
        for (int mt = 0; mt < 2; mt++) {
            int r0 = r0b + mt * 16;
            const unsigned* p0 = xproj + (size_t)nbs[r0 * KNBR + t] * 256;
            const unsigned* p1 = xproj + (size_t)nbs[(r0 + 8) * KNBR + t] * 256;
#pragma unroll
            for (int nt = 0; nt < 8; nt++) {
                int up = (nt >> 1) * 64 + wc * 8 + (nt & 1) * 4 + t4;
                d16[mt][nt][0] = p0[up];
                d16[mt][nt][1] = p1[up];
            }
        }
        if (t > 0) {
            const uint4* Ab = Af + (((t & 1) ^ 1) ? 32 * AFS : 0);
#pragma unroll
            for (int c = 0; c < 8; c++) {
                uint4 a[2];
#pragma unroll
                for (int mt = 0; mt < 2; mt++)
                    a[mt] = Ab[(c * 4 + t4) * AFS + (g * 2 + mt) * 8 + g4];
                const unsigned* bp = Wf + (c * 4 + t4) * WFS * 2;
#pragma unroll
                for (int nt = 0; nt < 8; nt++) {
                    int n = (nt >> 1) * 128 + wc * 16 + (nt & 1) * 8 + g4;
                    uint2 b = *(const uint2*)(bp + n * 2);
#pragma unroll
                    for (int mt = 0; mt < 2; mt++)
                        mma_f16a(d16[mt][nt], (const unsigned*)&a[mt], b.x, b.y);
                }
            }
        }
        // gates fp32 (c-state fp32)
        uint4* Aw = Af + ((t & 1) ? 32 * AFS : 0);
#pragma unroll
        for (int mt = 0; mt < 2; mt++) {
            unsigned hfr[2][2];
#pragma unroll
            for (int j = 0; j < 2; j++) {
                float2 i0 = hf2f(d16[mt][0 + j][0]), i1 = hf2f(d16[mt][0 + j][1]);
                float2 f0 = hf2f(d16[mt][2 + j][0]), f1 = hf2f(d16[mt][2 + j][1]);
                float2 q0 = hf2f(d16[mt][4 + j][0]), q1 = hf2f(d16[mt][4 + j][1]);
                float2 o0 = hf2f(d16[mt][6 + j][0]), o1 = hf2f(d16[mt][6 + j][1]);
                float zi[4] = {i0.x, i0.y, i1.x, i1.y};
                float zf[4] = {f0.x, f0.y, f1.x, f1.y};
                float zg[4] = {q0.x, q0.y, q1.x, q1.y};
                float zo[4] = {o0.x, o0.y, o1.x, o1.y};
                float h[4];
#pragma unroll
                for (int e = 0; e < 4; e++) {
                    float i_ = sig_t(zi[e]);
                    float f_ = sig_t(zf[e]);
                    float g_ = tanha(zg[e]);
                    float o_ = sig_t(zo[e]);
                    float cc = f_ * cst[mt][j][e] + i_ * g_;
                    cst[mt][j][e] = cc;
                    h[e] = o_ * tanha(cc);
                }
                hfr[j][0] = pk_f16(h[0], h[1]);
                hfr[j][1] = pk_f16(h[2], h[3]);
            }
            Aw[(wc * 4 + t4) * AFS + (g * 2 + mt) * 8 + g4] =
                make_uint4(hfr[0][0], hfr[0][1], hfr[1][0], hfr[1][1]);
        }
        asm volatile("bar.sync %0, 256;" :: "r"(g + 1) : "memory");
    }

    // ---- final step t=15: exact f32-accumulate path ----
    {
        const int t = KNBR - 1;
        float d[2][8][4];
#pragma unroll
        for (int mt = 0; mt < 2; mt++) {
            int r0 = r0b + mt * 16;
            const unsigned* p0 = xproj + (size_t)nbs[r0 * KNBR + t] * 256;
            const unsigned* p1 = xproj + (size_t)nbs[(r0 + 8) * KNBR + t] * 256;
#pragma unroll
            for (int nt = 0; nt < 8; nt++) {
                int up = (nt >> 1) * 64 + wc * 8 + (nt & 1) * 4 + t4;
                float2 f0 = hf2f(p0[up]);
                float2 f1 = hf2f(p1[up]);
                d[mt][nt][0] = f0.x; d[mt][nt][1] = f0.y;
                d[mt][nt][2] = f1.x; d[mt][nt][3] = f1.y;
            }
        }
        const uint4* Ab = Af + (((t & 1) ^ 1) ? 32 * AFS : 0);
#pragma unroll
        for (int c = 0; c < 8; c++) {
            uint4 a[2];
#pragma unroll
            for (int mt = 0; mt < 2; mt++)
                a[mt] = Ab[(c * 4 + t4) * AFS + (g * 2 + mt) * 8 + g4];
            const unsigned* bp = Wf + (c * 4 + t4) * WFS * 2;
#pragma unroll
            for (int nt = 0; nt < 8; nt++) {
                int n = (nt >> 1) * 128 + wc * 16 + (nt & 1) * 8 + g4;
                uint2 b = *(const uint2*)(bp + n * 2);
#pragma unroll
                for (int mt = 0; mt < 2; mt++)
                    mma_f16(d[mt][nt], (const unsigned*)&a[mt], b.x, b.y);
            }
        }
#pragma unroll
        for (int mt = 0; mt < 2; mt++) {
            int r0 = r0b + mt * 16;
            int n0 = base + r0, n1 = n0 + 8;
#pragma unroll
            for (int j = 0; j < 2; j++) {
                float h[4];
#pragma unroll
                for (int e = 0; e < 4; e++) {
                    float i_ = sig_t(d[mt][0 + j][e]);
                    float f_ = sig_t(d[mt][2 + j][e]);
                    float g_ = tanha(d[mt][4 + j][e]);
                    float o_ = sig_t(d[mt][6 + j][e]);
                    float cc = f_ * cst[mt][j][e] + i_ * g_;
                    h[e] = o_ * tanha(cc);
                }
                int col = wc * 16 + j * 8 + t4 * 2;
                if (n0 < N_NODES)
                    *(float2*)(hout + (size_t)n0 * 128 + col) =
                        make_float2(h[0], h[1]);
                if (n1 < N_NODES)
                    *(float2*)(hout + (size_t)n1 * 128 + col) =
                        make_float2(h[2], h[3]);
            }
        }
    }
}

// ---------------- outproj: fp16 SIMT mma + BN partials (fused BN on X) ----
__global__ __launch_bounds__(256) void outproj_f16_kernel(
    const float* __restrict__ X,  const float* __restrict__ Wself,
    const float* __restrict__ bself,
    const float* __restrict__ Hn, const float* __restrict__ Wneigh,
    float* __restrict__ Y, float* __restrict__ psum, float* __restrict__ psq,
    const float* __restrict__ bst, const float* __restrict__ bgm,
    const float* __restrict__ bbt)
{
    __shared__ unsigned xa[128 * 68];
    __shared__ unsigned Wb[64 * 132];
    __shared__ float    bsm[128];
    const int tid = threadIdx.x, w = tid >> 5, lane = tid & 31;
    const int g4 = lane >> 2, t4 = lane & 3;
    const int m0 = blockIdx.x * 128;

    if (tid < 128) bsm[tid] = bself[tid];

    float d[8][2][4];
#pragma unroll
    for (int mt = 0; mt < 8; mt++)
#pragma unroll
        for (int nt = 0; nt < 2; nt++)
#pragma unroll
            for (int e = 0; e < 4; e++) d[mt][nt][e] = 0.f;

#pragma unroll 1
    for (int seg = 0; seg < 2; seg++) {
        const float* Ap = seg ? Hn : X;
        const float* Wp = seg ? Wneigh : Wself;
        if (seg) __syncthreads();
        for (int i = tid; i < 128 * 32; i += 256) {
            int row = i >> 5, q = i & 31, gm = m0 + row;
            float4 v = make_float4(0.f, 0.f, 0.f, 0.f);
            if (gm < N_NODES) {
                v = *(const float4*)(Ap + (size_t)gm * 128 + q * 4);
                if (!seg && bst) v = bn4(v, q * 4, bst, bgm, bbt);
            }
            xa[row * 68 + q * 2]     = pk_f16(v.x, v.y);
            xa[row * 68 + q * 2 + 1] = pk_f16(v.z, v.w);
        }
        for (int i = tid; i < 128 * 32; i += 256) {
            int n = i >> 5, q = i & 31;
            float4 v = *(const float4*)(Wp + (size_t)n * 128 + q * 4);
            Wb[(q * 2)     * 132 + n] = pk_f16(v.x, v.y);
            Wb[(q * 2 + 1) * 132 + n] = pk_f16(v.z, v.w);
        }
        __syncthreads();
#pragma unroll
        for (int c = 0; c < 8; c++) {
            const int k0 = c * 8 + t4;
            unsigned a[8][4];
#pragma unroll
            for (int mt = 0; mt < 8; mt++) {
                int rb = (mt * 16 + g4) * 68;
                a[mt][0] = xa[rb + k0];
                a[mt][1] = xa[rb + 8 * 68 + k0];
                a[mt][2] = xa[rb + k0 + 4];
                a[mt][3] = xa[rb + 8 * 68 + k0 + 4];
            }
#pragma unroll
            for (int nt = 0; nt < 2; nt++) {
                int n = w * 16 + nt * 8 + g4;
                unsigned bb0 = Wb[k0 * 132 + n];
                unsigned bb1 = Wb[(k0 + 4) * 132 + n];
#pragma unroll
                for (int mt = 0; mt < 8; mt++) mma_f16(d[mt][nt], a[mt], bb0, bb1);
            }
        }
    }
    float cs[2][2], cq[2][2];
#pragma unroll
    for (int nt = 0; nt < 2; nt++)
#pragma unroll
        for (int e = 0; e < 2; e++) { cs[nt][e] = 0.f; cq[nt][e] = 0.f; }
#pragma unroll
    for (int nt = 0; nt < 2; nt++) {
        int col = w * 16 + nt * 8 + t4 * 2;
        float bx = bsm[col], by = bsm[col + 1];
#pragma unroll
        for (int mt = 0; mt < 8; mt++) {
            int gm0 = m0 + mt * 16 + g4, gm1 = gm0 + 8;
            if (gm0 < N_NODES) {
                float v0 = d[mt][nt][0] + bx, v1 = d[mt][nt][1] + by;
                *(float2*)(Y + (size_t)gm0 * 128 + col) = make_float2(v0, v1);
                cs[nt][0] += v0; cq[nt][0] += v0 * v0;
                cs[nt][1] += v1; cq[nt][1] += v1 * v1;
            }
            if (gm1 < N_NODES) {
                float v0 = d[mt][nt][2] + bx, v1 = d[mt][nt][3] + by;
                *(float2*)(Y + (size_t)gm1 * 128 + col) = make_float2(v0, v1);
                cs[nt][0] += v0; cq[nt][0] += v0 * v0;
                cs[nt][1] += v1; cq[nt][1] += v1 * v1;
            }
        }
    }
#pragma unroll
    for (int o = 4; o <= 16; o <<= 1)
#pragma unroll
        for (int nt = 0; nt < 2; nt++)
#pragma unroll
            for (int e = 0; e < 2; e++) {
                cs[nt][e] += __shfl_xor_sync(0xffffffffu, cs[nt][e], o);
                cq[nt][e] += __shfl_xor_sync(0xffffffffu, cq[nt][e], o);
            }
    if (g4 == 0)
#pragma unroll
        for (int nt = 0; nt < 2; nt++) {
            int col = w * 16 + nt * 8 + t4 * 2;
            *(float2*)(psum + blockIdx.x * 128 + col) = make_float2(cs[nt][0], cs[nt][1]);
            *(float2*)(psq  + blockIdx.x * 128 + col) = make_float2(cq[nt][0], cq[nt][1]);
        }
}

__global__ void bn_reduce(const float* __restrict__ psum,
                          const float* __restrict__ psq,
                          float* __restrict__ stats)
{
    __shared__ float rs[16], rq[16];
    const int c = blockIdx.x, tid = threadIdx.x;
    float s = 0.f, s2 = 0.f;
    for (int b = tid; b < GM; b += 256) {
        s  += psum[b * 128 + c];
        s2 += psq [b * 128 + c];
    }
#pragma unroll
    for (int o = 16; o > 0; o >>= 1) {
        s  += __shfl_down_sync(0xffffffffu, s,  o);
        s2 += __shfl_down_sync(0xffffffffu, s2, o);
    }
    if ((tid & 31) == 0) { rs[tid >> 5] = s; rq[tid >> 5] = s2; }
    __syncthreads();
    if (tid == 0) {
        float ts = 0.f, tq = 0.f;
#pragma unroll
        for (int i = 0; i < 8; i++) { ts += rs[i]; tq += rq[i]; }
        float mean = ts / (float)N_NODES;
        float var  = tq / (float)N_NODES - mean * mean;
        if (var < 0.f) var = 0.f;
        stats[c] = mean;
        stats[128 + c] = rsqrtf(var + 1e-5f);
    }
}

__global__ void bn_apply(const float* __restrict__ X,
                         const float* __restrict__ stats,
                         const float* __restrict__ gamma,
                         const float* __restrict__ beta,
                         float* __restrict__ Y, int relu)
{
    size_t i = (size_t)blockIdx.x * blockDim.x + threadIdx.x;
    if (i * 4 >= (size_t)N_NODES * D) return;
    float4 v = ((const float4*)X)[i];
    int c = (int)((i * 4) & (D - 1));
    float r[4] = {v.x, v.y, v.z, v.w};
#pragma unroll
    for (int e = 0; e < 4; e++) {
        float y = (r[e] - stats[c + e]) * stats[128 + c + e] * gamma[c + e] + beta[c + e];
        if (relu) y = fmaxf(y, 0.f);
        r[e] = y;
    }
    ((float4*)Y)[i] = make_float4(r[0], r[1], r[2], r[3]);
}

extern "C" void kernel_launch(void* const* d_in, const int* in_sizes, int n_in,
                              void* d_out, int out_size)
{
    const float* in_feat = (const float*)d_in[0];
    const int*   nbr     = (const int*)  d_in[1];
    const float* Wih1    = (const float*)d_in[2];
    const float* Whh1    = (const float*)d_in[3];
    const float* bih1    = (const float*)d_in[4];
    const float* bhh1    = (const float*)d_in[5];
    const float* Wself1  = (const float*)d_in[6];
    const float* bself1  = (const float*)d_in[7];
    const float* Wneigh1 = (const float*)d_in[8];
    const float* gamma1  = (const float*)d_in[9];
    const float* beta1   = (const float*)d_in[10];
    const float* Wih2    = (const float*)d_in[11];
    const float* Whh2    = (const float*)d_in[12];
    const float* bih2    = (const float*)d_in[13];
    const float* bhh2    = (const float*)d_in[14];
    const float* Wself2  = (const float*)d_in[15];
    const float* bself2  = (const float*)d_in[16];
    const float* Wneigh2 = (const float*)d_in[17];
    const float* gamma2  = (const float*)d_in[18];
    const float* beta2   = (const float*)d_in[19];
    float* out = (float*)d_out;

    unsigned* xp;
    float *hn, *tmp, *tmp2, *ps, *pq, *st;
    cudaGetSymbolAddress((void**)&xp,   g_xproj);
    cudaGetSymbolAddress((void**)&hn,   g_hneigh);
    cudaGetSymbolAddress((void**)&tmp,  g_tmp);
    cudaGetSymbolAddress((void**)&tmp2, g_tmp2);
    cudaGetSymbolAddress((void**)&ps,   g_psum);
    cudaGetSymbolAddress((void**)&pq,   g_psq);
    cudaGetSymbolAddress((void**)&st,   g_stats);

    cudaFuncSetAttribute(lstm_f16_kernel,
                         cudaFuncAttributeMaxDynamicSharedMemorySize,
                         LSTM_SMEM_BYTES);

    dim3 gproj(GM, 4);
    int bn_blocks = (int)(((size_t)N_NODES * D / 4 + 255) / 256);

    noop_kernel<<<1, 32>>>();
    noop_kernel<<<1, 32>>>();

    // ---- layer 1 (BN1 deferred into layer-2 consumers) ----
    proj_f16_kernel   <<<gproj, 256>>>(in_feat, Wih1, bih1, bhh1, xp,
                                       nullptr, nullptr, nullptr);
    lstm_f16_kernel   <<<LBLK, 512, LSTM_SMEM_BYTES>>>(xp, nbr, Whh1, hn);
    outproj_f16_kernel<<<GM, 256>>>(in_feat, Wself1, bself1, hn, Wneigh1,
                                    tmp, ps, pq, nullptr, nullptr, nullptr);
    bn_reduce         <<<128, 256>>>(ps, pq, st);

    // ---- layer 2 (consumers apply BN1+ReLU on load) ----
    proj_f16_kernel   <<<gproj, 256>>>(tmp, Wih2, bih2, bhh2, xp,
                                       st, gamma1, beta1);
    lstm_f16_kernel   <<<LBLK, 512, LSTM_SMEM_BYTES>>>(xp, nbr, Whh2, hn);
    outproj_f16_kernel<<<GM, 256>>>(tmp, Wself2, bself2, hn, Wneigh2,
                                    tmp2, ps, pq, st, gamma1, beta1);
    bn_reduce         <<<128, 256>>>(ps, pq, st);
    bn_apply          <<<bn_blocks, 256>>>(tmp2, st, gamma2, beta2, out, 0);
}

// round 15
// speedup vs baseline: 1.1090x; 1.1090x over previous
#include <cuda_runtime.h>
#include <cuda_fp16.h>
#include <cstdint>

#define N_NODES 100000
#define KNBR    16
#define D       128
#define GM      782
#define LBLK    1563             // ceil(N/64)
#define PSM     148              // persistent blocks

__device__ unsigned g_xproj [(size_t)N_NODES * 256];   // fp16x2 pairs
__device__ float    g_hneigh[(size_t)N_NODES * D];
__device__ float    g_tmp   [(size_t)N_NODES * D];
__device__ float    g_tmp2  [(size_t)N_NODES * D];
__device__ float    g_psum  [GM * D];
__device__ float    g_psq   [GM * D];
__device__ float    g_stats [2 * D];

__device__ __forceinline__ float tanha(float x) {
    float r; asm("tanh.approx.f32 %0, %1;" : "=f"(r) : "f"(x)); return r;
}
__device__ __forceinline__ float sig_t(float x) {
    return fmaf(tanha(0.5f * x), 0.5f, 0.5f);
}
__device__ __forceinline__ unsigned pk_f16(float lo, float hi) {
    unsigned r; asm("cvt.rn.f16x2.f32 %0, %1, %2;" : "=r"(r) : "f"(hi), "f"(lo));
    return r;
}
__device__ __forceinline__ float2 hf2f(unsigned u) {
    __half2 h = *reinterpret_cast<__half2*>(&u);
    return __half22float2(h);
}
__device__ __forceinline__ void mma_f16(float* d, const unsigned* a,
                                        unsigned b0, unsigned b1) {
    asm volatile(
        "mma.sync.aligned.m16n8k16.row.col.f32.f16.f16.f32 "
        "{%0,%1,%2,%3}, {%4,%5,%6,%7}, {%8,%9}, {%0,%1,%2,%3};"
        : "+f"(d[0]), "+f"(d[1]), "+f"(d[2]), "+f"(d[3])
        : "r"(a[0]), "r"(a[1]), "r"(a[2]), "r"(a[3]), "r"(b0), "r"(b1));
}
__device__ __forceinline__ float4 bn4(float4 v, int c0,
                                      const float* st, const float* gm,
                                      const float* bt) {
    float* p = (float*)&v;
#pragma unroll
    for (int e = 0; e < 4; e++) {
        float y = (p[e] - st[c0 + e]) * st[128 + c0 + e] * gm[c0 + e] + bt[c0 + e];
        p[e] = fmaxf(y, 0.f);
    }
    return v;
}

__global__ void noop_kernel() {}

// ---------------- proj: fp16 SIMT mma (optional fused BN+ReLU on A) --------
__global__ __launch_bounds__(256) void proj_f16_kernel(
    const float* __restrict__ A, const float* __restrict__ W,
    const float* __restrict__ b1, const float* __restrict__ b2,
    unsigned* __restrict__ C,
    const float* __restrict__ bst, const float* __restrict__ bgm,
    const float* __restrict__ bbt)
{
    __shared__ unsigned xa[128 * 68];
    __shared__ unsigned Wb[64 * 132];
    __shared__ float    bsm[128];
    const int tid = threadIdx.x, w = tid >> 5, lane = tid & 31;
    const int g4 = lane >> 2, t4 = lane & 3;
    const int m0 = blockIdx.x * 128, n0 = blockIdx.y * 128;

    for (int i = tid; i < 128 * 32; i += 256) {
        int row = i >> 5, q = i & 31, gm = m0 + row;
        float4 v = make_float4(0.f, 0.f, 0.f, 0.f);
        if (gm < N_NODES) {
            v = *(const float4*)(A + (size_t)gm * 128 + q * 4);
            if (bst) v = bn4(v, q * 4, bst, bgm, bbt);
        }
        xa[row * 68 + q * 2]     = pk_f16(v.x, v.y);
        xa[row * 68 + q * 2 + 1] = pk_f16(v.z, v.w);
    }
    for (int i = tid; i < 128 * 32; i += 256) {
        int n = i >> 5, q = i & 31;
        float4 v = *(const float4*)(W + (size_t)(n0 + n) * 128 + q * 4);
        Wb[(q * 2)     * 132 + n] = pk_f16(v.x, v.y);
        Wb[(q * 2 + 1) * 132 + n] = pk_f16(v.z, v.w);
    }
    if (tid < 128) bsm[tid] = b1[n0 + tid] + b2[n0 + tid];
    __syncthreads();

    float d[8][2][4];
#pragma unroll
    for (int mt = 0; mt < 8; mt++)
#pragma unroll
        for (int nt = 0; nt < 2; nt++)
#pragma unroll
            for (int e = 0; e < 4; e++) d[mt][nt][e] = 0.f;

#pragma unroll
    for (int c = 0; c < 8; c++) {
        const int k0 = c * 8 + t4;
        unsigned a[8][4];
#pragma unroll
        for (int mt = 0; mt < 8; mt++) {
            int rb = (mt * 16 + g4) * 68;
            a[mt][0] = xa[rb + k0];
            a[mt][1] = xa[rb + 8 * 68 + k0];
            a[mt][2] = xa[rb + k0 + 4];
            a[mt][3] = xa[rb + 8 * 68 + k0 + 4];
        }
#pragma unroll
        for (int nt = 0; nt < 2; nt++) {
            int n = w * 16 + nt * 8 + g4;
            unsigned bb0 = Wb[k0 * 132 + n];
            unsigned bb1 = Wb[(k0 + 4) * 132 + n];
#pragma unroll
            for (int mt = 0; mt < 8; mt++) mma_f16(d[mt][nt], a[mt], bb0, bb1);
        }
    }
#pragma unroll
    for (int mt = 0; mt < 8; mt++)
#pragma unroll
        for (int nt = 0; nt < 2; nt++) {
            int col = w * 16 + nt * 8 + t4 * 2;
            float bx = bsm[col], by = bsm[col + 1];
            int cp = (n0 + col) >> 1;
            int gm0 = m0 + mt * 16 + g4, gm1 = gm0 + 8;
            if (gm0 < N_NODES)
                C[(size_t)gm0 * 256 + cp] = pk_f16(d[mt][nt][0] + bx, d[mt][nt][1] + by);
            if (gm1 < N_NODES)
                C[(size_t)gm1 * 256 + cp] = pk_f16(d[mt][nt][2] + bx, d[mt][nt][3] + by);
        }
}

// ---------------- lstm: R11 core, persistent blocks (grid=148) -------------
#define WFS 516
#define AFS 34
#define WF_U32 (32 * WFS * 2)
#define AF_OFF WF_U32
#define AF_U32 (2 * 32 * AFS * 4)
#define NB_OFF (WF_U32 + AF_U32)
#define LSTM_SMEM_BYTES ((NB_OFF + 64 * KNBR) * 4)

__global__ __launch_bounds__(512, 1) void lstm_f16_kernel(
    const unsigned* __restrict__ xproj,  // [N,256] fp16x2, biases folded in
    const int*      __restrict__ nbr,
    const float*    __restrict__ Whh,    // [512,128]
    float*          __restrict__ hout)
{
    extern __shared__ unsigned smu[];
    unsigned* Wf  = smu;
    uint4*    Af  = (uint4*)(smu + AF_OFF);
    int*      nbs = (int*)(smu + NB_OFF);

    const int tid  = threadIdx.x;
    const int w    = tid >> 5;
    const int lane = tid & 31;
    const int g4   = lane >> 2;
    const int t4   = lane & 3;
    const int g    = w & 1;           // row group
    const int wc   = w >> 1;          // column slice
    const int lt   = (w >> 1) * 32 + lane;   // thread id within group 0..255

    // stage Whh once per persistent block
    {
        const float4* wp = (const float4*)(Whh + (size_t)tid * 128);
#pragma unroll 8
        for (int q = 0; q < 32; q++) {
            float4 v = wp[q];
            int kp0 = 2 * q, kp1 = 2 * q + 1;
            Wf[(((kp0 >> 3) * 4 + (kp0 & 3)) * WFS + tid) * 2 + ((kp0 >> 2) & 1)]
                = pk_f16(v.x, v.y);
            Wf[(((kp1 >> 3) * 4 + (kp1 & 3)) * WFS + tid) * 2 + ((kp1 >> 2) & 1)]
                = pk_f16(v.z, v.w);
        }
    }
    __syncthreads();

    const int r0b = g * 32 + g4;

#pragma unroll 1
    for (int tile = blockIdx.x; tile < LBLK; tile += PSM) {
        const int base = tile * 64;

        // group loads its own 32 nbs rows (rows g*32..g*32+32)
#pragma unroll
        for (int q = 0; q < 2; q++) {
            int i = lt + q * 256;            // 0..511 -> 32 rows x 16
            int r = g * 32 + (i >> 4);
            int nid = base + r;
            if (nid >= N_NODES) nid = N_NODES - 1;
            nbs[r * KNBR + (i & 15)] = nbr[(size_t)nid * KNBR + (i & 15)];
        }
        asm volatile("bar.sync %0, 256;" :: "r"(g + 1) : "memory");

        float cst[2][2][4];
#pragma unroll
        for (int mt = 0; mt < 2; mt++)
#pragma unroll
            for (int j = 0; j < 2; j++)
#pragma unroll
                for (int e = 0; e < 4; e++) cst[mt][j][e] = 0.f;

#pragma unroll 1
        for (int t = 0; t < KNBR; t++) {
            float d[2][8][4];
#pragma unroll
            for (int mt = 0; mt < 2; mt++) {
                int r0 = r0b + mt * 16;
                const unsigned* p0 = xproj + (size_t)nbs[r0 * KNBR + t] * 256;
                const unsigned* p1 = xproj + (size_t)nbs[(r0 + 8) * KNBR + t] * 256;
#pragma unroll
                for (int nt = 0; nt < 8; nt++) {
                    int up = (nt >> 1) * 64 + wc * 8 + (nt & 1) * 4 + t4;
                    float2 f0 = hf2f(p0[up]);
                    float2 f1 = hf2f(p1[up]);
                    d[mt][nt][0] = f0.x; d[mt][nt][1] = f0.y;
                    d[mt][nt][2] = f1.x; d[mt][nt][3] = f1.y;
                }
            }

            if (t > 0) {
                const uint4* Ab = Af + (((t & 1) ^ 1) ? 32 * AFS : 0);
#pragma unroll
                for (int c = 0; c < 8; c++) {
                    uint4 a[2];
#pragma unroll
                    for (int mt = 0; mt < 2; mt++)
                        a[mt] = Ab[(c * 4 + t4) * AFS + (g * 2 + mt) * 8 + g4];
                    const unsigned* bp = Wf + (c * 4 + t4) * WFS * 2;
#pragma unroll
                    for (int nt = 0; nt < 8; nt++) {
                        int n = (nt >> 1) * 128 + wc * 16 + (nt & 1) * 8 + g4;
                        uint2 b = *(const uint2*)(bp + n * 2);
#pragma unroll
                        for (int mt = 0; mt < 2; mt++)
                            mma_f16(d[mt][nt], (const unsigned*)&a[mt], b.x, b.y);
                    }
                }
            }

            uint4* Aw = Af + ((t & 1) ? 32 * AFS : 0);
#pragma unroll
            for (int mt = 0; mt < 2; mt++) {
                float h[2][4];
#pragma unroll
                for (int j = 0; j < 2; j++)
#pragma unroll
                    for (int e = 0; e < 4; e++) {
                        float i_ = sig_t(d[mt][0 + j][e]);
                        float f_ = sig_t(d[mt][2 + j][e]);
                        float g_ = tanha(d[mt][4 + j][e]);
                        float o_ = sig_t(d[mt][6 + j][e]);
                        float cc = f_ * cst[mt][j][e] + i_ * g_;
                        cst[mt][j][e] = cc;
                        h[j][e] = o_ * tanha(cc);
                    }
                if (t < KNBR - 1) {
                    Aw[(wc * 4 + t4) * AFS + (g * 2 + mt) * 8 + g4] =
                        make_uint4(pk_f16(h[0][0], h[0][1]), pk_f16(h[0][2], h[0][3]),
                                   pk_f16(h[1][0], h[1][1]), pk_f16(h[1][2], h[1][3]));
                } else {
                    int r0 = r0b + mt * 16;
                    int n0 = base + r0, n1 = n0 + 8;
#pragma unroll
                    for (int j = 0; j < 2; j++) {
                        int col = wc * 16 + j * 8 + t4 * 2;
                        if (n0 < N_NODES)
                            *(float2*)(hout + (size_t)n0 * 128 + col) =
                                make_float2(h[j][0], h[j][1]);
                        if (n1 < N_NODES)
                            *(float2*)(hout + (size_t)n1 * 128 + col) =
                                make_float2(h[j][2], h[j][3]);
                    }
                }
            }
            if (t < KNBR - 1)
                asm volatile("bar.sync %0, 256;" :: "r"(g + 1) : "memory");
        }
        // protect Af buffer 0 + nbs before next tile overwrites them
        asm volatile("bar.sync %0, 256;" :: "r"(g + 1) : "memory");
    }
}

// ---------------- outproj: fp16 SIMT mma + BN partials (fused BN on X) ----
__global__ __launch_bounds__(256) void outproj_f16_kernel(
    const float* __restrict__ X,  const float* __restrict__ Wself,
    const float* __restrict__ bself,
    const float* __restrict__ Hn, const float* __restrict__ Wneigh,
    float* __restrict__ Y, float* __restrict__ psum, float* __restrict__ psq,
    const float* __restrict__ bst, const float* __restrict__ bgm,
    const float* __restrict__ bbt)
{
    __shared__ unsigned xa[128 * 68];
    __shared__ unsigned Wb[64 * 132];
    __shared__ float    bsm[128];
    const int tid = threadIdx.x, w = tid >> 5, lane = tid & 31;
    const int g4 = lane >> 2, t4 = lane & 3;
    const int m0 = blockIdx.x * 128;

    if (tid < 128) bsm[tid] = bself[tid];

    float d[8][2][4];
#pragma unroll
    for (int mt = 0; mt < 8; mt++)
#pragma unroll
        for (int nt = 0; nt < 2; nt++)
#pragma unroll
            for (int e = 0; e < 4; e++) d[mt][nt][e] = 0.f;

#pragma unroll 1
    for (int seg = 0; seg < 2; seg++) {
        const float* Ap = seg ? Hn : X;
        const float* Wp = seg ? Wneigh : Wself;
        if (seg) __syncthreads();
        for (int i = tid; i < 128 * 32; i += 256) {
            int row = i >> 5, q = i & 31, gm = m0 + row;
            float4 v = make_float4(0.f, 0.f, 0.f, 0.f);
            if (gm < N_NODES) {
                v = *(const float4*)(Ap + (size_t)gm * 128 + q * 4);
                if (!seg && bst) v = bn4(v, q * 4, bst, bgm, bbt);
            }
            xa[row * 68 + q * 2]     = pk_f16(v.x, v.y);
            xa[row * 68 + q * 2 + 1] = pk_f16(v.z, v.w);
        }
        for (int i = tid; i < 128 * 32; i += 256) {
            int n = i >> 5, q = i & 31;
            float4 v = *(const float4*)(Wp + (size_t)n * 128 + q * 4);
            Wb[(q * 2)     * 132 + n] = pk_f16(v.x, v.y);
            Wb[(q * 2 + 1) * 132 + n] = pk_f16(v.z, v.w);
        }
        __syncthreads();
#pragma unroll
        for (int c = 0; c < 8; c++) {
            const int k0 = c * 8 + t4;
            unsigned a[8][4];
#pragma unroll
            for (int mt = 0; mt < 8; mt++) {
                int rb = (mt * 16 + g4) * 68;
                a[mt][0] = xa[rb + k0];
                a[mt][1] = xa[rb + 8 * 68 + k0];
                a[mt][2] = xa[rb + k0 + 4];
                a[mt][3] = xa[rb + 8 * 68 + k0 + 4];
            }
#pragma unroll
            for (int nt = 0; nt < 2; nt++) {
                int n = w * 16 + nt * 8 + g4;
                unsigned bb0 = Wb[k0 * 132 + n];
                unsigned bb1 = Wb[(k0 + 4) * 132 + n];
#pragma unroll
                for (int mt = 0; mt < 8; mt++) mma_f16(d[mt][nt], a[mt], bb0, bb1);
            }
        }
    }
    float cs[2][2], cq[2][2];
#pragma unroll
    for (int nt = 0; nt < 2; nt++)
#pragma unroll
        for (int e = 0; e < 2; e++) { cs[nt][e] = 0.f; cq[nt][e] = 0.f; }
#pragma unroll
    for (int nt = 0; nt < 2; nt++) {
        int col = w * 16 + nt * 8 + t4 * 2;
        float bx = bsm[col], by = bsm[col + 1];
#pragma unroll
        for (int mt = 0; mt < 8; mt++) {
            int gm0 = m0 + mt * 16 + g4, gm1 = gm0 + 8;
            if (gm0 < N_NODES) {
                float v0 = d[mt][nt][0] + bx, v1 = d[mt][nt][1] + by;
                *(float2*)(Y + (size_t)gm0 * 128 + col) = make_float2(v0, v1);
                cs[nt][0] += v0; cq[nt][0] += v0 * v0;
                cs[nt][1] += v1; cq[nt][1] += v1 * v1;
            }
            if (gm1 < N_NODES) {
                float v0 = d[mt][nt][2] + bx, v1 = d[mt][nt][3] + by;
                *(float2*)(Y + (size_t)gm1 * 128 + col) = make_float2(v0, v1);
                cs[nt][0] += v0; cq[nt][0] += v0 * v0;
                cs[nt][1] += v1; cq[nt][1] += v1 * v1;
            }
        }
    }
#pragma unroll
    for (int o = 4; o <= 16; o <<= 1)
#pragma unroll
        for (int nt = 0; nt < 2; nt++)
#pragma unroll
            for (int e = 0; e < 2; e++) {
                cs[nt][e] += __shfl_xor_sync(0xffffffffu, cs[nt][e], o);
                cq[nt][e] += __shfl_xor_sync(0xffffffffu, cq[nt][e], o);
            }
    if (g4 == 0)
#pragma unroll
        for (int nt = 0; nt < 2; nt++) {
            int col = w * 16 + nt * 8 + t4 * 2;
            *(float2*)(psum + blockIdx.x * 128 + col) = make_float2(cs[nt][0], cs[nt][1]);
            *(float2*)(psq  + blockIdx.x * 128 + col) = make_float2(cq[nt][0], cq[nt][1]);
        }
}

__global__ void bn_reduce(const float* __restrict__ psum,
                          const float* __restrict__ psq,
                          float* __restrict__ stats)
{
    __shared__ float rs[16], rq[16];
    const int c = blockIdx.x, tid = threadIdx.x;
    float s = 0.f, s2 = 0.f;
    for (int b = tid; b < GM; b += 256) {
        s  += psum[b * 128 + c];
        s2 += psq [b * 128 + c];
    }
#pragma unroll
    for (int o = 16; o > 0; o >>= 1) {
        s  += __shfl_down_sync(0xffffffffu, s,  o);
        s2 += __shfl_down_sync(0xffffffffu, s2, o);
    }
    if ((tid & 31) == 0) { rs[tid >> 5] = s; rq[tid >> 5] = s2; }
    __syncthreads();
    if (tid == 0) {
        float ts = 0.f, tq = 0.f;
#pragma unroll
        for (int i = 0; i < 8; i++) { ts += rs[i]; tq += rq[i]; }
        float mean = ts / (float)N_NODES;
        float var  = tq / (float)N_NODES - mean * mean;
        if (var < 0.f) var = 0.f;
        stats[c] = mean;
        stats[128 + c] = rsqrtf(var + 1e-5f);
    }
}

__global__ void bn_apply(const float* __restrict__ X,
                         const float* __restrict__ stats,
                         const float* __restrict__ gamma,
                         const float* __restrict__ beta,
                         float* __restrict__ Y, int relu)
{
    size_t i = (size_t)blockIdx.x * blockDim.x + threadIdx.x;
    if (i * 4 >= (size_t)N_NODES * D) return;
    float4 v = ((const float4*)X)[i];
    int c = (int)((i * 4) & (D - 1));
    float r[4] = {v.x, v.y, v.z, v.w};
#pragma unroll
    for (int e = 0; e < 4; e++) {
        float y = (r[e] - stats[c + e]) * stats[128 + c + e] * gamma[c + e] + beta[c + e];
        if (relu) y = fmaxf(y, 0.f);
        r[e] = y;
    }
    ((float4*)Y)[i] = make_float4(r[0], r[1], r[2], r[3]);
}

extern "C" void kernel_launch(void* const* d_in, const int* in_sizes, int n_in,
                              void* d_out, int out_size)
{
    const float* in_feat = (const float*)d_in[0];
    const int*   nbr     = (const int*)  d_in[1];
    const float* Wih1    = (const float*)d_in[2];
    const float* Whh1    = (const float*)d_in[3];
    const float* bih1    = (const float*)d_in[4];
    const float* bhh1    = (const float*)d_in[5];
    const float* Wself1  = (const float*)d_in[6];
    const float* bself1  = (const float*)d_in[7];
    const float* Wneigh1 = (const float*)d_in[8];
    const float* gamma1  = (const float*)d_in[9];
    const float* beta1   = (const float*)d_in[10];
    const float* Wih2    = (const float*)d_in[11];
    const float* Whh2    = (const float*)d_in[12];
    const float* bih2    = (const float*)d_in[13];
    const float* bhh2    = (const float*)d_in[14];
    const float* Wself2  = (const float*)d_in[15];
    const float* bself2  = (const float*)d_in[16];
    const float* Wneigh2 = (const float*)d_in[17];
    const float* gamma2  = (const float*)d_in[18];
    const float* beta2   = (const float*)d_in[19];
    float* out = (float*)d_out;

    unsigned* xp;
    float *hn, *tmp, *tmp2, *ps, *pq, *st;
    cudaGetSymbolAddress((void**)&xp,   g_xproj);
    cudaGetSymbolAddress((void**)&hn,   g_hneigh);
    cudaGetSymbolAddress((void**)&tmp,  g_tmp);
    cudaGetSymbolAddress((void**)&tmp2, g_tmp2);
    cudaGetSymbolAddress((void**)&ps,   g_psum);
    cudaGetSymbolAddress((void**)&pq,   g_psq);
    cudaGetSymbolAddress((void**)&st,   g_stats);

    cudaFuncSetAttribute(lstm_f16_kernel,
                         cudaFuncAttributeMaxDynamicSharedMemorySize,
                         LSTM_SMEM_BYTES);

    dim3 gproj(GM, 4);
    int bn_blocks = (int)(((size_t)N_NODES * D / 4 + 255) / 256);

    noop_kernel<<<1, 32>>>();
    noop_kernel<<<1, 32>>>();

    // ---- layer 1 (BN1 deferred into layer-2 consumers) ----
    proj_f16_kernel   <<<gproj, 256>>>(in_feat, Wih1, bih1, bhh1, xp,
                                       nullptr, nullptr, nullptr);
    lstm_f16_kernel   <<<PSM, 512, LSTM_SMEM_BYTES>>>(xp, nbr, Whh1, hn);
    outproj_f16_kernel<<<GM, 256>>>(in_feat, Wself1, bself1, hn, Wneigh1,
                                    tmp, ps, pq, nullptr, nullptr, nullptr);
    bn_reduce         <<<128, 256>>>(ps, pq, st);

    // ---- layer 2 (consumers apply BN1+ReLU on load) ----
    proj_f16_kernel   <<<gproj, 256>>>(tmp, Wih2, bih2, bhh2, xp,
                                       st, gamma1, beta1);
    lstm_f16_kernel   <<<PSM, 512, LSTM_SMEM_BYTES>>>(xp, nbr, Whh2, hn);
    outproj_f16_kernel<<<GM, 256>>>(tmp, Wself2, bself2, hn, Wneigh2,
                                    tmp2, ps, pq, st, gamma1, beta1);
    bn_reduce         <<<128, 256>>>(ps, pq, st);
    bn_apply          <<<bn_blocks, 256>>>(tmp2, st, gamma2, beta2, out, 0);
}

// round 17
// speedup vs baseline: 1.1138x; 1.0044x over previous
#include <cuda_runtime.h>
#include <cuda_fp16.h>
#include <cstdint>

#define N_NODES 100000
#define KNBR    16
#define D       128
#define GM      782
#define LBLK    1563             // ceil(N/64)
#define PSM     148              // persistent blocks

__device__ unsigned g_xproj [(size_t)N_NODES * 256];   // fp16x2 pairs
__device__ float    g_hneigh[(size_t)N_NODES * D];
__device__ float    g_tmp   [(size_t)N_NODES * D];
__device__ float    g_tmp2  [(size_t)N_NODES * D];
__device__ float    g_psum  [GM * D];
__device__ float    g_psq   [GM * D];
__device__ float    g_stats [2 * D];

__device__ __forceinline__ float tanha(float x) {
    float r; asm("tanh.approx.f32 %0, %1;" : "=f"(r) : "f"(x)); return r;
}
__device__ __forceinline__ float sig_t(float x) {
    return fmaf(tanha(0.5f * x), 0.5f, 0.5f);
}
__device__ __forceinline__ unsigned pk_f16(float lo, float hi) {
    unsigned r; asm("cvt.rn.f16x2.f32 %0, %1, %2;" : "=r"(r) : "f"(hi), "f"(lo));
    return r;
}
__device__ __forceinline__ float2 hf2f(unsigned u) {
    __half2 h = *reinterpret_cast<__half2*>(&u);
    return __half22float2(h);
}
__device__ __forceinline__ void mma_f16(float* d, const unsigned* a,
                                        unsigned b0, unsigned b1) {
    asm volatile(
        "mma.sync.aligned.m16n8k16.row.col.f32.f16.f16.f32 "
        "{%0,%1,%2,%3}, {%4,%5,%6,%7}, {%8,%9}, {%0,%1,%2,%3};"
        : "+f"(d[0]), "+f"(d[1]), "+f"(d[2]), "+f"(d[3])
        : "r"(a[0]), "r"(a[1]), "r"(a[2]), "r"(a[3]), "r"(b0), "r"(b1));
}
__device__ __forceinline__ float4 bn4(float4 v, int c0,
                                      const float* st, const float* gm,
                                      const float* bt) {
    float* p = (float*)&v;
#pragma unroll
    for (int e = 0; e < 4; e++) {
        float y = (p[e] - st[c0 + e]) * st[128 + c0 + e] * gm[c0 + e] + bt[c0 + e];
        p[e] = fmaxf(y, 0.f);
    }
    return v;
}

__global__ void noop_kernel() {}

// ---------------- proj: fp16 SIMT mma (optional fused BN+ReLU on A) --------
__global__ __launch_bounds__(256) void proj_f16_kernel(
    const float* __restrict__ A, const float* __restrict__ W,
    const float* __restrict__ b1, const float* __restrict__ b2,
    unsigned* __restrict__ C,
    const float* __restrict__ bst, const float* __restrict__ bgm,
    const float* __restrict__ bbt)
{
    __shared__ unsigned xa[128 * 68];
    __shared__ unsigned Wb[64 * 132];
    __shared__ float    bsm[128];
    const int tid = threadIdx.x, w = tid >> 5, lane = tid & 31;
    const int g4 = lane >> 2, t4 = lane & 3;
    const int m0 = blockIdx.x * 128, n0 = blockIdx.y * 128;

    for (int i = tid; i < 128 * 32; i += 256) {
        int row = i >> 5, q = i & 31, gm = m0 + row;
        float4 v = make_float4(0.f, 0.f, 0.f, 0.f);
        if (gm < N_NODES) {
            v = *(const float4*)(A + (size_t)gm * 128 + q * 4);
            if (bst) v = bn4(v, q * 4, bst, bgm, bbt);
        }
        xa[row * 68 + q * 2]     = pk_f16(v.x, v.y);
        xa[row * 68 + q * 2 + 1] = pk_f16(v.z, v.w);
    }
    for (int i = tid; i < 128 * 32; i += 256) {
        int n = i >> 5, q = i & 31;
        float4 v = *(const float4*)(W + (size_t)(n0 + n) * 128 + q * 4);
        Wb[(q * 2)     * 132 + n] = pk_f16(v.x, v.y);
        Wb[(q * 2 + 1) * 132 + n] = pk_f16(v.z, v.w);
    }
    if (tid < 128) bsm[tid] = b1[n0 + tid] + b2[n0 + tid];
    __syncthreads();

    float d[8][2][4];
#pragma unroll
    for (int mt = 0; mt < 8; mt++)
#pragma unroll
        for (int nt = 0; nt < 2; nt++)
#pragma unroll
            for (int e = 0; e < 4; e++) d[mt][nt][e] = 0.f;

#pragma unroll
    for (int c = 0; c < 8; c++) {
        const int k0 = c * 8 + t4;
        unsigned a[8][4];
#pragma unroll
        for (int mt = 0; mt < 8; mt++) {
            int rb = (mt * 16 + g4) * 68;
            a[mt][0] = xa[rb + k0];
            a[mt][1] = xa[rb + 8 * 68 + k0];
            a[mt][2] = xa[rb + k0 + 4];
            a[mt][3] = xa[rb + 8 * 68 + k0 + 4];
        }
#pragma unroll
        for (int nt = 0; nt < 2; nt++) {
            int n = w * 16 + nt * 8 + g4;
            unsigned bb0 = Wb[k0 * 132 + n];
            unsigned bb1 = Wb[(k0 + 4) * 132 + n];
#pragma unroll
            for (int mt = 0; mt < 8; mt++) mma_f16(d[mt][nt], a[mt], bb0, bb1);
        }
    }
#pragma unroll
    for (int mt = 0; mt < 8; mt++)
#pragma unroll
        for (int nt = 0; nt < 2; nt++) {
            int col = w * 16 + nt * 8 + t4 * 2;
            float bx = bsm[col], by = bsm[col + 1];
            int cp = (n0 + col) >> 1;
            int gm0 = m0 + mt * 16 + g4, gm1 = gm0 + 8;
            if (gm0 < N_NODES)
                C[(size_t)gm0 * 256 + cp] = pk_f16(d[mt][nt][0] + bx, d[mt][nt][1] + by);
            if (gm1 < N_NODES)
                C[(size_t)gm1 * 256 + cp] = pk_f16(d[mt][nt][2] + bx, d[mt][nt][3] + by);
        }
}

// ---------------- lstm: R15 core + group phase-stagger ---------------------
#define WFS 516
#define AFS 34
#define WF_U32 (32 * WFS * 2)
#define AF_OFF WF_U32
#define AF_U32 (2 * 32 * AFS * 4)
#define NB_OFF (WF_U32 + AF_U32)
#define LSTM_SMEM_BYTES ((NB_OFF + 64 * KNBR) * 4)

__global__ __launch_bounds__(512, 1) void lstm_f16_kernel(
    const unsigned* __restrict__ xproj,  // [N,256] fp16x2, biases folded in
    const int*      __restrict__ nbr,
    const float*    __restrict__ Whh,    // [512,128]
    float*          __restrict__ hout)
{
    extern __shared__ unsigned smu[];
    unsigned* Wf  = smu;
    uint4*    Af  = (uint4*)(smu + AF_OFF);
    int*      nbs = (int*)(smu + NB_OFF);

    const int tid  = threadIdx.x;
    const int w    = tid >> 5;
    const int lane = tid & 31;
    const int g4   = lane >> 2;
    const int t4   = lane & 3;
    const int g    = w & 1;           // row group
    const int wc   = w >> 1;          // column slice
    const int lt   = (w >> 1) * 32 + lane;

    // stage Whh once per persistent block
    {
        const float4* wp = (const float4*)(Whh + (size_t)tid * 128);
#pragma unroll 8
        for (int q = 0; q < 32; q++) {
            float4 v = wp[q];
            int kp0 = 2 * q, kp1 = 2 * q + 1;
            Wf[(((kp0 >> 3) * 4 + (kp0 & 3)) * WFS + tid) * 2 + ((kp0 >> 2) & 1)]
                = pk_f16(v.x, v.y);
            Wf[(((kp1 >> 3) * 4 + (kp1 & 3)) * WFS + tid) * 2 + ((kp1 >> 2) & 1)]
                = pk_f16(v.z, v.w);
        }
    }
    __syncthreads();

    // de-phase: group 1 lags ~1 gate-phase so its mma overlays group 0's
    // gates for the rest of the kernel (groups are independent chains).
    if (g == 1) __nanosleep(1200);

    const int r0b = g * 32 + g4;

#pragma unroll 1
    for (int tile = blockIdx.x; tile < LBLK; tile += PSM) {
        const int base = tile * 64;

#pragma unroll
        for (int q = 0; q < 2; q++) {
            int i = lt + q * 256;
            int r = g * 32 + (i >> 4);
            int nid = base + r;
            if (nid >= N_NODES) nid = N_NODES - 1;
            nbs[r * KNBR + (i & 15)] = nbr[(size_t)nid * KNBR + (i & 15)];
        }
        asm volatile("bar.sync %0, 256;" :: "r"(g + 1) : "memory");

        float cst[2][2][4];
#pragma unroll
        for (int mt = 0; mt < 2; mt++)
#pragma unroll
            for (int j = 0; j < 2; j++)
#pragma unroll
                for (int e = 0; e < 4; e++) cst[mt][j][e] = 0.f;

#pragma unroll 1
        for (int t = 0; t < KNBR; t++) {
            float d[2][8][4];
#pragma unroll
            for (int mt = 0; mt < 2; mt++) {
                int r0 = r0b + mt * 16;
                const unsigned* p0 = xproj + (size_t)nbs[r0 * KNBR + t] * 256;
                const unsigned* p1 = xproj + (size_t)nbs[(r0 + 8) * KNBR + t] * 256;
#pragma unroll
                for (int nt = 0; nt < 8; nt++) {
                    int up = (nt >> 1) * 64 + wc * 8 + (nt & 1) * 4 + t4;
                    float2 f0 = hf2f(p0[up]);
                    float2 f1 = hf2f(p1[up]);
                    d[mt][nt][0] = f0.x; d[mt][nt][1] = f0.y;
                    d[mt][nt][2] = f1.x; d[mt][nt][3] = f1.y;
                }
            }

            if (t > 0) {
                const uint4* Ab = Af + (((t & 1) ^ 1) ? 32 * AFS : 0);
#pragma unroll
                for (int c = 0; c < 8; c++) {
                    uint4 a[2];
#pragma unroll
                    for (int mt = 0; mt < 2; mt++)
                        a[mt] = Ab[(c * 4 + t4) * AFS + (g * 2 + mt) * 8 + g4];
                    const unsigned* bp = Wf + (c * 4 + t4) * WFS * 2;
#pragma unroll
                    for (int nt = 0; nt < 8; nt++) {
                        int n = (nt >> 1) * 128 + wc * 16 + (nt & 1) * 8 + g4;
                        uint2 b = *(const uint2*)(bp + n * 2);
#pragma unroll
                        for (int mt = 0; mt < 2; mt++)
                            mma_f16(d[mt][nt], (const unsigned*)&a[mt], b.x, b.y);
                    }
                }
            }

            uint4* Aw = Af + ((t & 1) ? 32 * AFS : 0);
#pragma unroll
            for (int mt = 0; mt < 2; mt++) {
                float h[2][4];
#pragma unroll
                for (int j = 0; j < 2; j++)
#pragma unroll
                    for (int e = 0; e < 4; e++) {
                        float i_ = sig_t(d[mt][0 + j][e]);
                        float f_ = sig_t(d[mt][2 + j][e]);
                        float g_ = tanha(d[mt][4 + j][e]);
                        float o_ = sig_t(d[mt][6 + j][e]);
                        float cc = f_ * cst[mt][j][e] + i_ * g_;
                        cst[mt][j][e] = cc;
                        h[j][e] = o_ * tanha(cc);
                    }
                if (t < KNBR - 1) {
                    Aw[(wc * 4 + t4) * AFS + (g * 2 + mt) * 8 + g4] =
                        make_uint4(pk_f16(h[0][0], h[0][1]), pk_f16(h[0][2], h[0][3]),
                                   pk_f16(h[1][0], h[1][1]), pk_f16(h[1][2], h[1][3]));
                } else {
                    int r0 = r0b + mt * 16;
                    int n0 = base + r0, n1 = n0 + 8;
#pragma unroll
                    for (int j = 0; j < 2; j++) {
                        int col = wc * 16 + j * 8 + t4 * 2;
                        if (n0 < N_NODES)
                            *(float2*)(hout + (size_t)n0 * 128 + col) =
                                make_float2(h[j][0], h[j][1]);
                        if (n1 < N_NODES)
                            *(float2*)(hout + (size_t)n1 * 128 + col) =
                                make_float2(h[j][2], h[j][3]);
                    }
                }
            }
            if (t < KNBR - 1)
                asm volatile("bar.sync %0, 256;" :: "r"(g + 1) : "memory");
        }
        asm volatile("bar.sync %0, 256;" :: "r"(g + 1) : "memory");
    }
}

// ---------------- outproj: fp16 SIMT mma + BN partials (fused BN on X) ----
__global__ __launch_bounds__(256) void outproj_f16_kernel(
    const float* __restrict__ X,  const float* __restrict__ Wself,
    const float* __restrict__ bself,
    const float* __restrict__ Hn, const float* __restrict__ Wneigh,
    float* __restrict__ Y, float* __restrict__ psum, float* __restrict__ psq,
    const float* __restrict__ bst, const float* __restrict__ bgm,
    const float* __restrict__ bbt)
{
    __shared__ unsigned xa[128 * 68];
    __shared__ unsigned Wb[64 * 132];
    __shared__ float    bsm[128];
    const int tid = threadIdx.x, w = tid >> 5, lane = tid & 31;
    const int g4 = lane >> 2, t4 = lane & 3;
    const int m0 = blockIdx.x * 128;

    if (tid < 128) bsm[tid] = bself[tid];

    float d[8][2][4];
#pragma unroll
    for (int mt = 0; mt < 8; mt++)
#pragma unroll
        for (int nt = 0; nt < 2; nt++)
#pragma unroll
            for (int e = 0; e < 4; e++) d[mt][nt][e] = 0.f;

#pragma unroll 1
    for (int seg = 0; seg < 2; seg++) {
        const float* Ap = seg ? Hn : X;
        const float* Wp = seg ? Wneigh : Wself;
        if (seg) __syncthreads();
        for (int i = tid; i < 128 * 32; i += 256) {
            int row = i >> 5, q = i & 31, gm = m0 + row;
            float4 v = make_float4(0.f, 0.f, 0.f, 0.f);
            if (gm < N_NODES) {
                v = *(const float4*)(Ap + (size_t)gm * 128 + q * 4);
                if (!seg && bst) v = bn4(v, q * 4, bst, bgm, bbt);
            }
            xa[row * 68 + q * 2]     = pk_f16(v.x, v.y);
            xa[row * 68 + q * 2 + 1] = pk_f16(v.z, v.w);
        }
        for (int i = tid; i < 128 * 32; i += 256) {
            int n = i >> 5, q = i & 31;
            float4 v = *(const float4*)(Wp + (size_t)n * 128 + q * 4);
            Wb[(q * 2)     * 132 + n] = pk_f16(v.x, v.y);
            Wb[(q * 2 + 1) * 132 + n] = pk_f16(v.z, v.w);
        }
        __syncthreads();
#pragma unroll
        for (int c = 0; c < 8; c++) {
            const int k0 = c * 8 + t4;
            unsigned a[8][4];
#pragma unroll
            for (int mt = 0; mt < 8; mt++) {
                int rb = (mt * 16 + g4) * 68;
                a[mt][0] = xa[rb + k0];
                a[mt][1] = xa[rb + 8 * 68 + k0];
                a[mt][2] = xa[rb + k0 + 4];
                a[mt][3] = xa[rb + 8 * 68 + k0 + 4];
            }
#pragma unroll
            for (int nt = 0; nt < 2; nt++) {
                int n = w * 16 + nt * 8 + g4;
                unsigned bb0 = Wb[k0 * 132 + n];
                unsigned bb1 = Wb[(k0 + 4) * 132 + n];
#pragma unroll
                for (int mt = 0; mt < 8; mt++) mma_f16(d[mt][nt], a[mt], bb0, bb1);
            }
        }
    }
    float cs[2][2], cq[2][2];
#pragma unroll
    for (int nt = 0; nt < 2; nt++)
#pragma unroll
        for (int e = 0; e < 2; e++) { cs[nt][e] = 0.f; cq[nt][e] = 0.f; }
#pragma unroll
    for (int nt = 0; nt < 2; nt++) {
        int col = w * 16 + nt * 8 + t4 * 2;
        float bx = bsm[col], by = bsm[col + 1];
#pragma unroll
        for (int mt = 0; mt < 8; mt++) {
            int gm0 = m0 + mt * 16 + g4, gm1 = gm0 + 8;
            if (gm0 < N_NODES) {
                float v0 = d[mt][nt][0] + bx, v1 = d[mt][nt][1] + by;
                *(float2*)(Y + (size_t)gm0 * 128 + col) = make_float2(v0, v1);
                cs[nt][0] += v0; cq[nt][0] += v0 * v0;
                cs[nt][1] += v1; cq[nt][1] += v1 * v1;
            }
            if (gm1 < N_NODES) {
                float v0 = d[mt][nt][2] + bx, v1 = d[mt][nt][3] + by;
                *(float2*)(Y + (size_t)gm1 * 128 + col) = make_float2(v0, v1);
                cs[nt][0] += v0; cq[nt][0] += v0 * v0;
                cs[nt][1] += v1; cq[nt][1] += v1 * v1;
            }
        }
    }
#pragma unroll
    for (int o = 4; o <= 16; o <<= 1)
#pragma unroll
        for (int nt = 0; nt < 2; nt++)
#pragma unroll
            for (int e = 0; e < 2; e++) {
                cs[nt][e] += __shfl_xor_sync(0xffffffffu, cs[nt][e], o);
                cq[nt][e] += __shfl_xor_sync(0xffffffffu, cq[nt][e], o);
            }
    if (g4 == 0)
#pragma unroll
        for (int nt = 0; nt < 2; nt++) {
            int col = w * 16 + nt * 8 + t4 * 2;
            *(float2*)(psum + blockIdx.x * 128 + col) = make_float2(cs[nt][0], cs[nt][1]);
            *(float2*)(psq  + blockIdx.x * 128 + col) = make_float2(cq[nt][0], cq[nt][1]);
        }
}

__global__ void bn_reduce(const float* __restrict__ psum,
                          const float* __restrict__ psq,
                          float* __restrict__ stats)
{
    __shared__ float rs[16], rq[16];
    const int c = blockIdx.x, tid = threadIdx.x;
    float s = 0.f, s2 = 0.f;
    for (int b = tid; b < GM; b += 256) {
        s  += psum[b * 128 + c];
        s2 += psq [b * 128 + c];
    }
#pragma unroll
    for (int o = 16; o > 0; o >>= 1) {
        s  += __shfl_down_sync(0xffffffffu, s,  o);
        s2 += __shfl_down_sync(0xffffffffu, s2, o);
    }
    if ((tid & 31) == 0) { rs[tid >> 5] = s; rq[tid >> 5] = s2; }
    __syncthreads();
    if (tid == 0) {
        float ts = 0.f, tq = 0.f;
#pragma unroll
        for (int i = 0; i < 8; i++) { ts += rs[i]; tq += rq[i]; }
        float mean = ts / (float)N_NODES;
        float var  = tq / (float)N_NODES - mean * mean;
        if (var < 0.f) var = 0.f;
        stats[c] = mean;
        stats[128 + c] = rsqrtf(var + 1e-5f);
    }
}

__global__ void bn_apply(const float* __restrict__ X,
                         const float* __restrict__ stats,
                         const float* __restrict__ gamma,
                         const float* __restrict__ beta,
                         float* __restrict__ Y, int relu)
{
    size_t i = (size_t)blockIdx.x * blockDim.x + threadIdx.x;
    if (i * 4 >= (size_t)N_NODES * D) return;
    float4 v = ((const float4*)X)[i];
    int c = (int)((i * 4) & (D - 1));
    float r[4] = {v.x, v.y, v.z, v.w};
#pragma unroll
    for (int e = 0; e < 4; e++) {
        float y = (r[e] - stats[c + e]) * stats[128 + c + e] * gamma[c + e] + beta[c + e];
        if (relu) y = fmaxf(y, 0.f);
        r[e] = y;
    }
    ((float4*)Y)[i] = make_float4(r[0], r[1], r[2], r[3]);
}

extern "C" void kernel_launch(void* const* d_in, const int* in_sizes, int n_in,
                              void* d_out, int out_size)
{
    const float* in_feat = (const float*)d_in[0];
    const int*   nbr     = (const int*)  d_in[1];
    const float* Wih1    = (const float*)d_in[2];
    const float* Whh1    = (const float*)d_in[3];
    const float* bih1    = (const float*)d_in[4];
    const float* bhh1    = (const float*)d_in[5];
    const float* Wself1  = (const float*)d_in[6];
    const float* bself1  = (const float*)d_in[7];
    const float* Wneigh1 = (const float*)d_in[8];
    const float* gamma1  = (const float*)d_in[9];
    const float* beta1   = (const float*)d_in[10];
    const float* Wih2    = (const float*)d_in[11];
    const float* Whh2    = (const float*)d_in[12];
    const float* bih2    = (const float*)d_in[13];
    const float* bhh2    = (const float*)d_in[14];
    const float* Wself2  = (const float*)d_in[15];
    const float* bself2  = (const float*)d_in[16];
    const float* Wneigh2 = (const float*)d_in[17];
    const float* gamma2  = (const float*)d_in[18];
    const float* beta2   = (const float*)d_in[19];
    float* out = (float*)d_out;

    unsigned* xp;
    float *hn, *tmp, *tmp2, *ps, *pq, *st;
    cudaGetSymbolAddress((void**)&xp,   g_xproj);
    cudaGetSymbolAddress((void**)&hn,   g_hneigh);
    cudaGetSymbolAddress((void**)&tmp,  g_tmp);
    cudaGetSymbolAddress((void**)&tmp2, g_tmp2);
    cudaGetSymbolAddress((void**)&ps,   g_psum);
    cudaGetSymbolAddress((void**)&pq,   g_psq);
    cudaGetSymbolAddress((void**)&st,   g_stats);

    cudaFuncSetAttribute(lstm_f16_kernel,
                         cudaFuncAttributeMaxDynamicSharedMemorySize,
                         LSTM_SMEM_BYTES);

    dim3 gproj(GM, 4);
    int bn_blocks = (int)(((size_t)N_NODES * D / 4 + 255) / 256);

    noop_kernel<<<1, 32>>>();
    noop_kernel<<<1, 32>>>();

    // ---- layer 1 (BN1 deferred into layer-2 consumers) ----
    proj_f16_kernel   <<<gproj, 256>>>(in_feat, Wih1, bih1, bhh1, xp,
                                       nullptr, nullptr, nullptr);
    lstm_f16_kernel   <<<PSM, 512, LSTM_SMEM_BYTES>>>(xp, nbr, Whh1, hn);
    outproj_f16_kernel<<<GM, 256>>>(in_feat, Wself1, bself1, hn, Wneigh1,
                                    tmp, ps, pq, nullptr, nullptr, nullptr);
    bn_reduce         <<<128, 256>>>(ps, pq, st);

    // ---- layer 2 (consumers apply BN1+ReLU on load) ----
    proj_f16_kernel   <<<gproj, 256>>>(tmp, Wih2, bih2, bhh2, xp,
                                       st, gamma1, beta1);
    lstm_f16_kernel   <<<PSM, 512, LSTM_SMEM_BYTES>>>(xp, nbr, Whh2, hn);
    outproj_f16_kernel<<<GM, 256>>>(tmp, Wself2, bself2, hn, Wneigh2,
                                    tmp2, ps, pq, st, gamma1, beta1);
    bn_reduce         <<<128, 256>>>(ps, pq, st);
    bn_apply          <<<bn_blocks, 256>>>(tmp2, st, gamma2, beta2, out, 0);
}